// round 8
// baseline (speedup 1.0000x reference)
#include <cuda_runtime.h>
#include <math.h>
#include <float.h>
#include <stdint.h>

#define VOCAB 32000
#define HID   1024
#define BEAM  16
#define TSTEPS 16
#define NLB 125   // logits blocks (125*256 == 32000)

// ---------------- device scratch ----------------
__device__ float g_tv[BEAM * BEAM];
__device__ int   g_ti[BEAM * BEAM];
__device__ int   g_seq[TSTEPS * BEAM];
__device__ float g_seqlp[TSTEPS * BEAM];
__device__ float g_lps[BEAM];
__device__ int   g_tok[BEAM];
__device__ int   g_perm[BEAM];
__device__ float g_st2[2][HID * BEAM];             // hidden state double buffer [k][b]
__device__ unsigned long long g_h2[HID * 8];       // h packed beam-pairs [k][bp]
__device__ unsigned long long g_bkeys[NLB * BEAM * 16]; // per-block sorted top16
__device__ float2 g_bstat[NLB * BEAM];             // per-block (max, sumexp)
__device__ unsigned g_ctr;                         // reduce completion counter

// ---------------- helpers ----------------
__device__ __forceinline__ unsigned long long pack_key(float v, unsigned idx_inv) {
    unsigned u = __float_as_uint(v);
    u = (u & 0x80000000u) ? ~u : (u | 0x80000000u);
    return ((unsigned long long)u << 32) | (unsigned long long)idx_inv;
}
__device__ __forceinline__ float unpack_val(unsigned long long k) {
    unsigned u = (unsigned)(k >> 32);
    u = (u & 0x80000000u) ? (u ^ 0x80000000u) : ~u;
    return __uint_as_float(u);
}
__device__ __forceinline__ unsigned long long pack2f(float lo, float hi) {
    unsigned long long r;
    asm("mov.b64 %0, {%1, %2};" : "=l"(r) : "r"(__float_as_uint(lo)), "r"(__float_as_uint(hi)));
    return r;
}
__device__ __forceinline__ void unpack2(unsigned long long a, float& lo, float& hi) {
    unsigned ulo, uhi;
    asm("mov.b64 {%0, %1}, %2;" : "=r"(ulo), "=r"(uhi) : "l"(a));
    lo = __uint_as_float(ulo); hi = __uint_as_float(uhi);
}
__device__ __forceinline__ unsigned long long fma2(unsigned long long a, unsigned long long b,
                                                   unsigned long long c) {
    unsigned long long d;
    asm("fma.rn.f32x2 %0, %1, %2, %3;" : "=l"(d) : "l"(a), "l"(b), "l"(c));
    return d;
}
__device__ __forceinline__ unsigned long long add2(unsigned long long a, unsigned long long b) {
    unsigned long long d;
    asm("add.rn.f32x2 %0, %1, %2;" : "=l"(d) : "l"(a), "l"(b));
    return d;
}
__device__ __forceinline__ void cp16(unsigned saddr, const void* gaddr) {
    asm volatile("cp.async.cg.shared.global [%0], [%1], 16;" :: "r"(saddr), "l"(gaddr));
}
__device__ __forceinline__ unsigned long long warpMaxU64(unsigned long long v) {
    #pragma unroll
    for (int o = 16; o; o >>= 1) {
        unsigned long long w = __shfl_xor_sync(0xffffffffu, v, o);
        if (w > v) v = w;
    }
    return v;
}
__device__ __forceinline__ unsigned long long blockMaxU64(unsigned long long v) {
    __shared__ unsigned long long red[8]; __shared__ unsigned long long out;
    v = warpMaxU64(v);
    if ((threadIdx.x & 31) == 0) red[threadIdx.x >> 5] = v;
    __syncthreads();
    if (threadIdx.x < 32) {
        unsigned long long w = (threadIdx.x < 8) ? red[threadIdx.x] : 0ull;
        #pragma unroll
        for (int o = 4; o; o >>= 1) {
            unsigned long long t = __shfl_down_sync(0xffffffffu, w, o);
            if (t > w) w = t;
        }
        if (threadIdx.x == 0) out = w;
    }
    __syncthreads();
    unsigned long long r = out; __syncthreads();
    return r;
}

#define CE(a, b) { unsigned long long _mx = (a) > (b) ? (a) : (b); \
                   unsigned long long _mn = (a) > (b) ? (b) : (a); (a) = _mx; (b) = _mn; }
#define SORT8(s0,s1,s2,s3,s4,s5,s6,s7) \
    CE(s0,s1) CE(s2,s3) CE(s4,s5) CE(s6,s7) \
    CE(s0,s2) CE(s1,s3) CE(s4,s6) CE(s5,s7) \
    CE(s1,s2) CE(s5,s6) CE(s0,s4) CE(s3,s7) \
    CE(s1,s5) CE(s2,s6) \
    CE(s1,s4) CE(s3,s6) \
    CE(s2,s4) CE(s3,s5) \
    CE(s3,s4)

// shared select logic (callable from k_select and k_reduce tail)
__device__ void select_body(int t) {
    int tid = threadIdx.x;
    int q = tid >> 4;
    float tvv = g_tv[tid];
    float cv = g_lps[q] + tvv;
    if (t == 0 && q != 0) cv = -INFINITY;
    unsigned long long key = pack_key(cv, 0xFFFFFFFFu - (unsigned)tid);

    __shared__ int   s_q[16], s_c[16];
    __shared__ float s_r[16], s_nl[16];

    unsigned long long prev = ~0ull;
    for (int r = 0; r < 16; r++) {
        unsigned long long h = (key < prev) ? key : 0ull;
        unsigned long long win = blockMaxU64(h);
        if (h == win && h != 0ull) {
            int c = g_ti[tid];
            s_q[r] = q; s_c[r] = c; s_r[r] = tvv;
            s_nl[r] = (c == 0 || t == TSTEPS - 1) ? -1000.0f : cv;
        }
        prev = win;
    }
    __syncthreads();

    __shared__ int   oseq[256];
    __shared__ float oslp[256];
    oseq[tid] = g_seq[tid];
    oslp[tid] = g_seqlp[tid];
    __syncthreads();

    int row = tid >> 4, j = tid & 15;
    if (row < t) {
        g_seq[tid]   = oseq[row * 16 + s_q[j]];
        g_seqlp[tid] = oslp[row * 16 + s_q[j]];
    } else if (row == t) {
        g_seq[tid]   = s_c[j];
        g_seqlp[tid] = s_r[j];
    }
    if (tid < 16) {
        g_lps[tid]  = s_nl[tid];
        g_tok[tid]  = s_c[tid];
        g_perm[tid] = s_q[tid];
    }
}

// ---------------- kernels ----------------

// init + per-row stats/top16 over EXTERNAL logprobs (16 blocks x 256)
__global__ void k_begin(const float* __restrict__ state,
                        const float* __restrict__ ext) {
    int row = blockIdx.x, tid = threadIdx.x;
    int gi = row * 256 + tid;
    // ---- init ----
    #pragma unroll
    for (int r = 0; r < 4; r++) {
        int i = gi * 4 + r;
        if (i < HID * BEAM) {
            int k = i >> 4, b = i & 15;
            g_st2[0][i] = state[b * HID + k];
        }
    }
    if (gi < TSTEPS * BEAM) { g_seq[gi] = 0; g_seqlp[gi] = 0.0f; }
    if (gi < BEAM) g_lps[gi] = 0.0f;
    if (gi == 0) g_ctr = 0;

    // ---- stats + top16 for this row ----
    const float* __restrict__ src = ext + (size_t)row * VOCAB;
    __shared__ unsigned long long cand[16 * 256];
    #pragma unroll
    for (int j = 0; j < 16; j++) cand[j * 256 + tid] = 0ull;
    unsigned long long s15 = 0ull;

    float m = -FLT_MAX, s = 0.0f;
    for (int c = tid; c < VOCAB; c += 256) {
        float z = src[c];
        if (z > m) { s = s * expf(m - z) + 1.0f; m = z; }
        else       { s += expf(z - m); }
        float v = (c == VOCAB - 1) ? z - 1000.0f : z;
        unsigned long long key = pack_key(v, 0xFFFFFFFFu - (unsigned)c);
        if (key > s15) {
            int j = 15;
            while (j > 0 && cand[(j - 1) * 256 + tid] < key) {
                cand[j * 256 + tid] = cand[(j - 1) * 256 + tid];
                j--;
            }
            cand[j * 256 + tid] = key;
            s15 = cand[15 * 256 + tid];
        }
    }
    __shared__ float rm[8], rs[8]; __shared__ float s_off;
    #pragma unroll
    for (int o = 16; o; o >>= 1) {
        float m2 = __shfl_down_sync(0xffffffffu, m, o);
        float s2 = __shfl_down_sync(0xffffffffu, s, o);
        if (m2 > m) { s = s * expf(m - m2) + s2; m = m2; }
        else        { s += s2 * expf(m2 - m); }
    }
    if ((tid & 31) == 0) { rm[tid >> 5] = m; rs[tid >> 5] = s; }
    __syncthreads();
    if (tid == 0) {
        float mm = rm[0], ss = rs[0];
        for (int w = 1; w < 8; w++) {
            float m2 = rm[w], s2 = rs[w];
            if (m2 > mm) { ss = ss * expf(mm - m2) + s2; mm = m2; }
            else         { ss += s2 * expf(m2 - mm); }
        }
        s_off = mm + logf(ss);
    }
    __syncthreads();
    float off = s_off;

    unsigned long long prev = ~0ull;
    int p = 0;
    for (int r = 0; r < 16; r++) {
        while (p < 16 && cand[p * 256 + tid] >= prev) p++;
        unsigned long long h = (p < 16) ? cand[p * 256 + tid] : 0ull;
        unsigned long long win = blockMaxU64(h);
        if (tid == 0) {
            g_ti[row * 16 + r] = (int)(0xFFFFFFFFu - (unsigned)win);
            g_tv[row * 16 + r] = unpack_val(win) - off;
        }
        prev = win;
    }
}

__global__ void k_select(int t) { select_body(t); }

// RNN full-K GEMM + tanh. 64 blocks x 256 thr. Block = 16 cols, K=2048 in
// 4 phases of 512 k; W via cp.async double buffer; in-block k-split x16 with
// deterministic tree reduction. Writes g_st2[(t+1)&1] and g_h2.
// dyn smem: sx2 [0,32K) ; ws0 [32K,64K) ; ws1 [64K,96K)
__global__ void __launch_bounds__(256, 1) k_rnn(int t,
        const float* __restrict__ embed, const float* __restrict__ Wih,
        const float* __restrict__ Whh, const float* __restrict__ bvec) {
    extern __shared__ __align__(16) unsigned long long smem_rnn[];
    unsigned long long* sx2 = smem_rnn;                  // 4096 u64
    __shared__ int stok[16], sperm[16];

    int tid = threadIdx.x;
    int bx = blockIdx.x;
    if (tid < 16) stok[tid] = g_tok[tid];
    else if (tid < 32) sperm[tid - 16] = g_perm[tid - 16];
    const float* stprev = g_st2[t & 1];

    unsigned sbase;
    asm("{ .reg .u64 tt; cvta.to.shared.u64 tt, %1; cvt.u32.u64 %0, tt; }"
        : "=r"(sbase) : "l"(smem_rnn));

    // commit W phase 0
    {
        const float* Wsel = Wih;
        unsigned sb = sbase + 32768;
        #pragma unroll
        for (int i = 0; i < 8; i++) {
            int lin = i * 256 + tid;
            int rowr = lin >> 2, u = lin & 3;
            cp16(sb + rowr * 64 + u * 16,
                 Wsel + (size_t)rowr * HID + bx * 16 + u * 4);
        }
        asm volatile("cp.async.commit_group;");
    }

    unsigned long long acc[8];
    #pragma unroll
    for (int i = 0; i < 8; i++) acc[i] = 0ull;
    int col = tid & 15, ks = tid >> 4;

    for (int p = 0; p < 4; p++) {
        __syncthreads();   // sx2 free (prev compute done); stok ready
        // build x for this phase
        #pragma unroll
        for (int i = 0; i < 16; i++) {
            int lin = i * 256 + tid;
            int k = lin >> 3, bp = lin & 7;
            int kg = p * 512 + k;
            float v0, v1;
            if (kg < HID) {
                v0 = __ldg(&embed[(size_t)stok[2 * bp] * HID + kg]);
                v1 = __ldg(&embed[(size_t)stok[2 * bp + 1] * HID + kg]);
            } else {
                v0 = stprev[(kg - HID) * 16 + sperm[2 * bp]];
                v1 = stprev[(kg - HID) * 16 + sperm[2 * bp + 1]];
            }
            sx2[k * 8 + bp] = pack2f(v0, v1);
        }
        // commit next W phase
        if (p < 3) {
            int pn = p + 1;
            int rowbase = (pn * 512) & 1023;
            const float* Wsel = (pn < 2) ? Wih : Whh;
            unsigned sb = sbase + 32768 + (pn & 1) * 32768;
            #pragma unroll
            for (int i = 0; i < 8; i++) {
                int lin = i * 256 + tid;
                int rowr = lin >> 2, u = lin & 3;
                cp16(sb + rowr * 64 + u * 16,
                     Wsel + (size_t)(rowbase + rowr) * HID + bx * 16 + u * 4);
            }
            asm volatile("cp.async.commit_group;");
            asm volatile("cp.async.wait_group 1;");
        } else {
            asm volatile("cp.async.wait_group 0;");
        }
        __syncthreads();

        const float* wb = (const float*)(smem_rnn + 4096 + (size_t)(p & 1) * 4096);
        #pragma unroll 8
        for (int kl = 0; kl < 32; kl++) {
            int k = ks * 32 + kl;
            float w = wb[k * 16 + col];
            unsigned long long wq = pack2f(w, w);
            const ulonglong2* hr = (const ulonglong2*)(sx2 + k * 8);
            ulonglong2 h01 = hr[0], h23 = hr[1], h45 = hr[2], h67 = hr[3];
            acc[0] = fma2(h01.x, wq, acc[0]); acc[1] = fma2(h01.y, wq, acc[1]);
            acc[2] = fma2(h23.x, wq, acc[2]); acc[3] = fma2(h23.y, wq, acc[3]);
            acc[4] = fma2(h45.x, wq, acc[4]); acc[5] = fma2(h45.y, wq, acc[5]);
            acc[6] = fma2(h67.x, wq, acc[6]); acc[7] = fma2(h67.y, wq, acc[7]);
        }
    }

    // deterministic tree reduction over ks (16-way), in ws0 region
    unsigned long long* sacc = smem_rnn + 4096;
    __syncthreads();
    #pragma unroll
    for (int i = 0; i < 8; i++) sacc[tid * 8 + i] = acc[i];
    #pragma unroll
    for (int off = 8; off; off >>= 1) {
        __syncthreads();
        if (ks < off) {
            int other = tid + off * 16;
            #pragma unroll
            for (int i = 0; i < 8; i++)
                sacc[tid * 8 + i] = add2(sacc[tid * 8 + i], sacc[other * 8 + i]);
        }
    }
    __syncthreads();
    if (tid < 16) {
        int colg = bx * 16 + tid;
        float bb = bvec[colg];
        float* stn = g_st2[(t + 1) & 1];
        #pragma unroll
        for (int jj = 0; jj < 8; jj++) {
            float a, bq;
            unpack2(sacc[tid * 8 + jj], a, bq);
            float h0 = tanhf(a + bb), h1 = tanhf(bq + bb);
            stn[colg * 16 + 2 * jj]     = h0;
            stn[colg * 16 + 2 * jj + 1] = h1;
            g_h2[colg * 8 + jj] = pack2f(h0, h1);
        }
    }
}

// logits GEMM + fused per-block stats & top-16 (round-6 variant).
// 125 blocks x 256 threads. smem: [0,64K) h2, [64K,128K) two 32KB W buffers.
__global__ void __launch_bounds__(256, 1) k_logits(const float* __restrict__ W) {
    extern __shared__ __align__(16) unsigned long long dynsmem[];
    __shared__ float sred[8 * 16];
    __shared__ float sbm[16];

    int tid = threadIdx.x;
    int lane = tid & 31, wid = tid >> 5;
    int col = blockIdx.x * 256 + tid;

    unsigned sbase;
    asm("{ .reg .u64 t; cvta.to.shared.u64 t, %1; cvt.u32.u64 %0, t; }"
        : "=r"(sbase) : "l"(dynsmem));

    {
        const float* gbase = W + (size_t)blockIdx.x * 256;
        unsigned sb = sbase + 65536;
        #pragma unroll
        for (int i = 0; i < 8; i++) {
            int lin = i * 256 + tid;
            int row = lin >> 6, cq = lin & 63;
            cp16(sb + (row << 10) + (cq << 4), gbase + (size_t)row * VOCAB + cq * 4);
        }
        asm volatile("cp.async.commit_group;");
    }
    #pragma unroll
    for (int i = 0; i < 32; i++) dynsmem[i * 256 + tid] = g_h2[i * 256 + tid];

    unsigned long long acc[8];
    #pragma unroll
    for (int i = 0; i < 8; i++) acc[i] = 0ull;

    for (int c = 0; c < 32; c++) {
        __syncthreads();
        if (c + 1 < 32) {
            const float* gbase = W + (size_t)((c + 1) * 32) * VOCAB + (size_t)blockIdx.x * 256;
            unsigned sb = sbase + 65536 + (((c + 1) & 1) << 15);
            #pragma unroll
            for (int i = 0; i < 8; i++) {
                int lin = i * 256 + tid;
                int row = lin >> 6, cq = lin & 63;
                cp16(sb + (row << 10) + (cq << 4), gbase + (size_t)row * VOCAB + cq * 4);
            }
            asm volatile("cp.async.commit_group;");
            asm volatile("cp.async.wait_group 1;");
        } else {
            asm volatile("cp.async.wait_group 0;");
        }
        __syncthreads();

        const float* wbuf = (const float*)((char*)dynsmem + 65536 + ((c & 1) << 15));
        const unsigned long long* hb = dynsmem + (size_t)c * 32 * 8;
        #pragma unroll
        for (int kk = 0; kk < 32; kk++) {
            float w = wbuf[kk * 256 + tid];
            unsigned long long wq = pack2f(w, w);
            const ulonglong2* hr = (const ulonglong2*)(hb + kk * 8);
            ulonglong2 h01 = hr[0], h23 = hr[1], h45 = hr[2], h67 = hr[3];
            acc[0] = fma2(h01.x, wq, acc[0]); acc[1] = fma2(h01.y, wq, acc[1]);
            acc[2] = fma2(h23.x, wq, acc[2]); acc[3] = fma2(h23.y, wq, acc[3]);
            acc[4] = fma2(h45.x, wq, acc[4]); acc[5] = fma2(h45.y, wq, acc[5]);
            acc[6] = fma2(h67.x, wq, acc[6]); acc[7] = fma2(h67.y, wq, acc[7]);
        }
    }

    float z[16];
    #pragma unroll
    for (int i = 0; i < 8; i++) unpack2(acc[i], z[2 * i], z[2 * i + 1]);

    #pragma unroll
    for (int b = 0; b < 16; b++) {
        float v = z[b];
        #pragma unroll
        for (int o = 16; o; o >>= 1) v = fmaxf(v, __shfl_xor_sync(0xffffffffu, v, o));
        if (lane == 0) sred[wid * 16 + b] = v;
    }
    __syncthreads();
    if (tid < 16) {
        float m = sred[tid];
        #pragma unroll
        for (int w = 1; w < 8; w++) m = fmaxf(m, sred[w * 16 + tid]);
        sbm[tid] = m;
    }
    __syncthreads();
    #pragma unroll
    for (int b = 0; b < 16; b++) {
        float e = expf(z[b] - sbm[b]);
        #pragma unroll
        for (int o = 16; o; o >>= 1) e += __shfl_xor_sync(0xffffffffu, e, o);
        if (lane == 0) sred[wid * 16 + b] = e;
    }
    __syncthreads();
    if (tid < 16) {
        float s = sred[tid];
        #pragma unroll
        for (int w = 1; w < 8; w++) s += sred[w * 16 + tid];
        g_bstat[blockIdx.x * 16 + tid] = make_float2(sbm[tid], s);
    }

    unsigned long long* skeys = dynsmem + 8192;
    #pragma unroll
    for (int b = 0; b < 16; b++) {
        float v = z[b];
        if (col == VOCAB - 1) v -= 1000.0f;
        skeys[b * 256 + tid] = pack_key(v, 0xFFFFFFFFu - (unsigned)col);
    }
    __syncthreads();

    #pragma unroll
    for (int bb = 0; bb < 2; bb++) {
        int b = wid * 2 + bb;
        const unsigned long long* kp = skeys + b * 256;
        unsigned long long s0 = kp[0 * 32 + lane], s1 = kp[1 * 32 + lane],
                           s2 = kp[2 * 32 + lane], s3 = kp[3 * 32 + lane],
                           s4 = kp[4 * 32 + lane], s5 = kp[5 * 32 + lane],
                           s6 = kp[6 * 32 + lane], s7 = kp[7 * 32 + lane];
        SORT8(s0, s1, s2, s3, s4, s5, s6, s7)
        #pragma unroll
        for (int r = 0; r < 16; r++) {
            unsigned long long win = warpMaxU64(s0);
            if (s0 == win) {
                s0 = s1; s1 = s2; s2 = s3; s3 = s4; s4 = s5; s5 = s6; s6 = s7; s7 = 0ull;
            }
            if (lane == r) g_bkeys[((size_t)blockIdx.x * 16 + b) * 16 + r] = win;
        }
    }
}

// combine 125 block partials per beam + (last block) run select(tsel)
__global__ void __launch_bounds__(256) k_reduce(int tsel) {
    int beam = blockIdx.x, tid = threadIdx.x;
    __shared__ float rm[8], rs[8]; __shared__ float s_off;

    float m = -FLT_MAX, s = 0.0f;
    if (tid < NLB) {
        float2 st = g_bstat[tid * 16 + beam];
        m = st.x; s = st.y;
    }
    #pragma unroll
    for (int o = 16; o; o >>= 1) {
        float m2 = __shfl_xor_sync(0xffffffffu, m, o);
        float s2 = __shfl_xor_sync(0xffffffffu, s, o);
        float mm = fmaxf(m, m2);
        s = s * expf(m - mm) + s2 * expf(m2 - mm);
        m = mm;
    }
    if ((tid & 31) == 0) { rm[tid >> 5] = m; rs[tid >> 5] = s; }
    __syncthreads();
    if (tid == 0) {
        float mm = rm[0], ss = rs[0];
        for (int w = 1; w < 8; w++) {
            float m2 = rm[w], s2 = rs[w];
            float mx = fmaxf(mm, m2);
            ss = ss * expf(mm - mx) + s2 * expf(m2 - mx);
            mm = mx;
        }
        s_off = mm + logf(ss);
    }
    __syncthreads();
    float off = s_off;

    unsigned long long s0 = 0, s1 = 0, s2 = 0, s3 = 0, s4 = 0, s5 = 0, s6 = 0, s7 = 0;
    int base = tid * 8;
    if (base < NLB * 16) {
        int blk = base >> 4, r0 = base & 15;
        const unsigned long long* kp = g_bkeys + ((size_t)blk * 16 + beam) * 16 + r0;
        s0 = kp[0]; s1 = kp[1]; s2 = kp[2]; s3 = kp[3];
        s4 = kp[4]; s5 = kp[5]; s6 = kp[6]; s7 = kp[7];
    }
    SORT8(s0, s1, s2, s3, s4, s5, s6, s7)
    for (int r = 0; r < 16; r++) {
        unsigned long long win = blockMaxU64(s0);
        if (s0 == win && win != 0ull) {
            s0 = s1; s1 = s2; s2 = s3; s3 = s4; s4 = s5; s5 = s6; s6 = s7; s7 = 0ull;
        }
        if (tid == 0) {
            g_ti[beam * 16 + r] = (int)(0xFFFFFFFFu - (unsigned)win);
            g_tv[beam * 16 + r] = unpack_val(win) - off;
        }
    }

    // ---- last-block select fold ----
    __shared__ unsigned s_last;
    __threadfence();
    __syncthreads();
    if (tid == 0) s_last = (atomicAdd(&g_ctr, 1u) == 15u) ? 1u : 0u;
    __syncthreads();
    if (!s_last) return;
    if (tid == 0) g_ctr = 0;
    __threadfence();
    select_body(tsel);
}

__global__ void k_final(float* __restrict__ out) {
    int i = threadIdx.x;
    for (int j = i; j < 528; j += 256) {
        if (j < 256)      out[j] = (float)g_seq[j];
        else if (j < 512) out[j] = g_seqlp[j - 256];
        else              out[j] = g_lps[j - 512];
    }
}

// ---------------- launch ----------------
extern "C" void kernel_launch(void* const* d_in, const int* in_sizes, int n_in,
                              void* d_out, int out_size) {
    const float* state    = (const float*)d_in[0];
    const float* logprobs = (const float*)d_in[1];
    const float* embed    = (const float*)d_in[2];
    const float* W_ih     = (const float*)d_in[3];
    const float* W_hh     = (const float*)d_in[4];
    const float* bvec     = (const float*)d_in[5];
    const float* W_out    = (const float*)d_in[6];
    float* out = (float*)d_out;
    (void)in_sizes; (void)n_in; (void)out_size;

    const int LOGITS_SMEM = 128 * 1024;
    const int RNN_SMEM    = 96 * 1024;
    cudaFuncSetAttribute(k_logits, cudaFuncAttributeMaxDynamicSharedMemorySize,
                         LOGITS_SMEM);
    cudaFuncSetAttribute(k_rnn, cudaFuncAttributeMaxDynamicSharedMemorySize,
                         RNN_SMEM);

    k_begin<<<16, 256>>>(state, logprobs);
    k_select<<<1, 256>>>(0);
    for (int t = 0; t < TSTEPS - 1; t++) {
        k_rnn<<<64, 256, RNN_SMEM>>>(t, embed, W_ih, W_hh, bvec);
        k_logits<<<NLB, 256, LOGITS_SMEM>>>(W_out);
        k_reduce<<<16, 256>>>(t + 1);   // folds select(t+1)
    }
    k_final<<<1, 256>>>(out);
}

// round 9
// speedup vs baseline: 1.2775x; 1.2775x over previous
#include <cuda_runtime.h>
#include <math.h>
#include <float.h>
#include <stdint.h>

#define VOCAB 32000
#define HID   1024
#define BEAM  16
#define TSTEPS 16
#define NLB 250   // logits blocks (250*128 == 32000)

// ---------------- device scratch ----------------
__device__ float g_tv[BEAM * BEAM];
__device__ int   g_ti[BEAM * BEAM];
__device__ int   g_seq[TSTEPS * BEAM];
__device__ float g_seqlp[TSTEPS * BEAM];
__device__ float g_lps[BEAM];
__device__ int   g_tok[BEAM];
__device__ int   g_perm[BEAM];
__device__ float g_st[HID * BEAM];                 // hidden state [k][b]
__device__ float g_racc[32 * HID * BEAM];          // rnn partials [p][col][b]
__device__ unsigned long long g_h2[HID * 8];       // h packed beam-pairs [k][bp]
__device__ unsigned long long g_bkeys[NLB * BEAM * 16]; // per-block sorted top16
__device__ float2 g_bstat[NLB * BEAM];             // per-block (max, sumexp)
__device__ unsigned g_ctr;                         // completion counter

// ---------------- helpers ----------------
__device__ __forceinline__ unsigned long long pack_key(float v, unsigned idx_inv) {
    unsigned u = __float_as_uint(v);
    u = (u & 0x80000000u) ? ~u : (u | 0x80000000u);
    return ((unsigned long long)u << 32) | (unsigned long long)idx_inv;
}
__device__ __forceinline__ float unpack_val(unsigned long long k) {
    unsigned u = (unsigned)(k >> 32);
    u = (u & 0x80000000u) ? (u ^ 0x80000000u) : ~u;
    return __uint_as_float(u);
}
__device__ __forceinline__ unsigned long long pack2f(float lo, float hi) {
    unsigned long long r;
    asm("mov.b64 %0, {%1, %2};" : "=l"(r) : "r"(__float_as_uint(lo)), "r"(__float_as_uint(hi)));
    return r;
}
__device__ __forceinline__ void unpack2(unsigned long long a, float& lo, float& hi) {
    unsigned ulo, uhi;
    asm("mov.b64 {%0, %1}, %2;" : "=r"(ulo), "=r"(uhi) : "l"(a));
    lo = __uint_as_float(ulo); hi = __uint_as_float(uhi);
}
__device__ __forceinline__ unsigned long long fma2(unsigned long long a, unsigned long long b,
                                                   unsigned long long c) {
    unsigned long long d;
    asm("fma.rn.f32x2 %0, %1, %2, %3;" : "=l"(d) : "l"(a), "l"(b), "l"(c));
    return d;
}
__device__ __forceinline__ void cp16(unsigned saddr, const void* gaddr) {
    asm volatile("cp.async.cg.shared.global [%0], [%1], 16;" :: "r"(saddr), "l"(gaddr));
}
__device__ __forceinline__ unsigned long long warpMaxU64(unsigned long long v) {
    #pragma unroll
    for (int o = 16; o; o >>= 1) {
        unsigned long long w = __shfl_xor_sync(0xffffffffu, v, o);
        if (w > v) v = w;
    }
    return v;
}
__device__ __forceinline__ unsigned long long blockMaxU64(unsigned long long v) {
    __shared__ unsigned long long red[8]; __shared__ unsigned long long out;
    v = warpMaxU64(v);
    if ((threadIdx.x & 31) == 0) red[threadIdx.x >> 5] = v;
    __syncthreads();
    if (threadIdx.x < 32) {
        unsigned long long w = (threadIdx.x < 8) ? red[threadIdx.x] : 0ull;
        #pragma unroll
        for (int o = 4; o; o >>= 1) {
            unsigned long long t = __shfl_down_sync(0xffffffffu, w, o);
            if (t > w) w = t;
        }
        if (threadIdx.x == 0) out = w;
    }
    __syncthreads();
    unsigned long long r = out; __syncthreads();
    return r;
}

#define CE(a, b) { unsigned long long _mx = (a) > (b) ? (a) : (b); \
                   unsigned long long _mn = (a) > (b) ? (b) : (a); (a) = _mx; (b) = _mn; }
#define SORT4(s0,s1,s2,s3) \
    CE(s0,s1) CE(s2,s3) CE(s0,s2) CE(s1,s3) CE(s1,s2)

// shared select logic
__device__ void select_body(int t) {
    int tid = threadIdx.x;
    int q = tid >> 4;
    float tvv = g_tv[tid];
    float cv = g_lps[q] + tvv;
    if (t == 0 && q != 0) cv = -INFINITY;
    unsigned long long key = pack_key(cv, 0xFFFFFFFFu - (unsigned)tid);

    __shared__ int   s_q[16], s_c[16];
    __shared__ float s_r[16], s_nl[16];

    unsigned long long prev = ~0ull;
    for (int r = 0; r < 16; r++) {
        unsigned long long h = (key < prev) ? key : 0ull;
        unsigned long long win = blockMaxU64(h);
        if (h == win && h != 0ull) {
            int c = g_ti[tid];
            s_q[r] = q; s_c[r] = c; s_r[r] = tvv;
            s_nl[r] = (c == 0 || t == TSTEPS - 1) ? -1000.0f : cv;
        }
        prev = win;
    }
    __syncthreads();

    __shared__ int   oseq[256];
    __shared__ float oslp[256];
    oseq[tid] = g_seq[tid];
    oslp[tid] = g_seqlp[tid];
    __syncthreads();

    int row = tid >> 4, j = tid & 15;
    if (row < t) {
        g_seq[tid]   = oseq[row * 16 + s_q[j]];
        g_seqlp[tid] = oslp[row * 16 + s_q[j]];
    } else if (row == t) {
        g_seq[tid]   = s_c[j];
        g_seqlp[tid] = s_r[j];
    }
    if (tid < 16) {
        g_lps[tid]  = s_nl[tid];
        g_tok[tid]  = s_c[tid];
        g_perm[tid] = s_q[tid];
    }
}

// ---------------- kernels ----------------

// init + per-row stats/top16 over EXTERNAL logprobs + fold select(0)
__global__ void k_begin(const float* __restrict__ state,
                        const float* __restrict__ ext) {
    int row = blockIdx.x, tid = threadIdx.x;
    int gi = row * 256 + tid;
    #pragma unroll
    for (int r = 0; r < 4; r++) {
        int i = gi * 4 + r;
        if (i < HID * BEAM) {
            int k = i >> 4, b = i & 15;
            g_st[i] = state[b * HID + k];
        }
    }
    if (gi < TSTEPS * BEAM) { g_seq[gi] = 0; g_seqlp[gi] = 0.0f; }
    if (gi < BEAM) g_lps[gi] = 0.0f;

    const float* __restrict__ src = ext + (size_t)row * VOCAB;
    __shared__ unsigned long long cand[16 * 256];
    #pragma unroll
    for (int j = 0; j < 16; j++) cand[j * 256 + tid] = 0ull;
    unsigned long long s15 = 0ull;

    float m = -FLT_MAX, s = 0.0f;
    for (int c = tid; c < VOCAB; c += 256) {
        float z = src[c];
        if (z > m) { s = s * expf(m - z) + 1.0f; m = z; }
        else       { s += expf(z - m); }
        float v = (c == VOCAB - 1) ? z - 1000.0f : z;
        unsigned long long key = pack_key(v, 0xFFFFFFFFu - (unsigned)c);
        if (key > s15) {
            int j = 15;
            while (j > 0 && cand[(j - 1) * 256 + tid] < key) {
                cand[j * 256 + tid] = cand[(j - 1) * 256 + tid];
                j--;
            }
            cand[j * 256 + tid] = key;
            s15 = cand[15 * 256 + tid];
        }
    }
    __shared__ float rm[8], rs[8]; __shared__ float s_off;
    #pragma unroll
    for (int o = 16; o; o >>= 1) {
        float m2 = __shfl_down_sync(0xffffffffu, m, o);
        float s2 = __shfl_down_sync(0xffffffffu, s, o);
        if (m2 > m) { s = s * expf(m - m2) + s2; m = m2; }
        else        { s += s2 * expf(m2 - m); }
    }
    if ((tid & 31) == 0) { rm[tid >> 5] = m; rs[tid >> 5] = s; }
    __syncthreads();
    if (tid == 0) {
        float mm = rm[0], ss = rs[0];
        for (int w = 1; w < 8; w++) {
            float m2 = rm[w], s2 = rs[w];
            if (m2 > mm) { ss = ss * expf(mm - m2) + s2; mm = m2; }
            else         { ss += s2 * expf(m2 - mm); }
        }
        s_off = mm + logf(ss);
    }
    __syncthreads();
    float off = s_off;

    unsigned long long prev = ~0ull;
    int p = 0;
    for (int r = 0; r < 16; r++) {
        while (p < 16 && cand[p * 256 + tid] >= prev) p++;
        unsigned long long h = (p < 16) ? cand[p * 256 + tid] : 0ull;
        unsigned long long win = blockMaxU64(h);
        if (tid == 0) {
            g_ti[row * 16 + r] = (int)(0xFFFFFFFFu - (unsigned)win);
            g_tv[row * 16 + r] = unpack_val(win) - off;
        }
        prev = win;
    }

    // fold select(0) into last-finishing block
    __shared__ unsigned s_last;
    __threadfence();
    __syncthreads();
    if (tid == 0) s_last = (atomicAdd(&g_ctr, 1u) == 15u) ? 1u : 0u;
    __syncthreads();
    if (!s_last) return;
    if (tid == 0) g_ctr = 0;
    __threadfence();
    select_body(0);
}

// RNN partial GEMM (round-6 proven). grid(8,16), 256 thr.
__global__ void __launch_bounds__(256, 1) k_rnn(const float* __restrict__ embed,
                                                const float* __restrict__ Wih,
                                                const float* __restrict__ Whh) {
    __shared__ unsigned long long sx2[128 * 8];   // [k][bp]
    int tid = threadIdx.x;
    int ks = blockIdx.y;

    for (int e = tid; e < 1024; e += 256) {
        int k = e >> 3, bp = e & 7;
        float v0, v1;
        if (ks < 8) {
            int kk = ks * 128 + k;
            v0 = __ldg(&embed[(size_t)g_tok[2 * bp] * HID + kk]);
            v1 = __ldg(&embed[(size_t)g_tok[2 * bp + 1] * HID + kk]);
        } else {
            int kk = (ks - 8) * 128 + k;
            v0 = g_st[kk * 16 + g_perm[2 * bp]];
            v1 = g_st[kk * 16 + g_perm[2 * bp + 1]];
        }
        sx2[e] = pack2f(v0, v1);
    }
    __syncthreads();

    int col = blockIdx.x * 128 + (tid & 127);
    int khalf = tid >> 7;
    int baserow = (ks & 7) * 128 + khalf * 64;
    const float* Wsel = (ks < 8) ? Wih : Whh;
    const float* wp = Wsel + (size_t)baserow * HID + col;

    unsigned long long acc[8];
    #pragma unroll
    for (int i = 0; i < 8; i++) acc[i] = 0ull;

    for (int k0 = 0; k0 < 64; k0 += 16) {
        float w[16];
        #pragma unroll
        for (int i = 0; i < 16; i++)
            w[i] = __ldg(wp + (size_t)(k0 + i) * HID);
        #pragma unroll
        for (int i = 0; i < 16; i++) {
            unsigned long long wq = pack2f(w[i], w[i]);
            const ulonglong2* hr = (const ulonglong2*)(sx2 + (khalf * 64 + k0 + i) * 8);
            ulonglong2 h01 = hr[0], h23 = hr[1], h45 = hr[2], h67 = hr[3];
            acc[0] = fma2(h01.x, wq, acc[0]); acc[1] = fma2(h01.y, wq, acc[1]);
            acc[2] = fma2(h23.x, wq, acc[2]); acc[3] = fma2(h23.y, wq, acc[3]);
            acc[4] = fma2(h45.x, wq, acc[4]); acc[5] = fma2(h45.y, wq, acc[5]);
            acc[6] = fma2(h67.x, wq, acc[6]); acc[7] = fma2(h67.y, wq, acc[7]);
        }
    }
    unsigned long long* dst = (unsigned long long*)g_racc
                            + ((size_t)(ks * 2 + khalf) * HID + col) * 8;
    #pragma unroll
    for (int bp = 0; bp < 8; bp++) dst[bp] = acc[bp];
}

// sum 32 partials + tanh -> g_st, pack h2
__global__ void k_rnnfin(const float* __restrict__ bvec) {
    int j = blockIdx.x * 256 + threadIdx.x;
    if (j >= HID * 8) return;
    int k = j >> 3, bp = j & 7;
    float a0 = 0.0f, a1 = 0.0f;
    #pragma unroll 8
    for (int p = 0; p < 32; p++) {
        float2 v = *(const float2*)&g_racc[((size_t)p * HID + k) * 16 + bp * 2];
        a0 += v.x; a1 += v.y;
    }
    float bb = bvec[k];
    float t0 = tanhf(a0 + bb), t1 = tanhf(a1 + bb);
    g_st[k * 16 + bp * 2]     = t0;
    g_st[k * 16 + bp * 2 + 1] = t1;
    g_h2[k * 8 + bp] = pack2f(t0, t1);
}

// logits GEMM + fused warp-local stats & top-16.
// 250 blocks x 256 thr (2 blocks/SM). Block = 128 cols; thread = (col, beamHalf):
// each warp accumulates 8 beams (2 h-broadcast LDS.128 per k). W via 4-deep
// cp.async ring of 8KB chunks, ONE barrier per chunk, 3 chunks in flight.
// dyn smem: [0,64K) h2 ; [64K,96K) ring (zbuf/skeys reuse after mainloop).
__global__ void __launch_bounds__(256, 2) k_logits(const float* __restrict__ W) {
    extern __shared__ __align__(16) unsigned long long dynsmem[];

    int tid = threadIdx.x;
    int lane = tid & 31, wid = tid >> 5;
    int colIdx = tid & 127;
    int half = tid >> 7;

    unsigned sbase;
    asm("{ .reg .u64 t; cvta.to.shared.u64 t, %1; cvt.u32.u64 %0, t; }"
        : "=r"(sbase) : "l"(dynsmem));
    const float* gcol = W + (size_t)blockIdx.x * 128;

    // preamble: commit chunks 0..2 (chunk = 16 k-rows x 128 cols = 8KB)
    #pragma unroll
    for (int c = 0; c < 3; c++) {
        unsigned sb = sbase + 65536 + c * 8192;
        #pragma unroll
        for (int i = 0; i < 2; i++) {
            int lin = i * 256 + tid;         // 512 x 16B
            int row = lin >> 5, u = lin & 31;
            cp16(sb + (row << 9) + (u << 4),
                 gcol + (size_t)(c * 16 + row) * VOCAB + u * 4);
        }
        asm volatile("cp.async.commit_group;");
    }
    // preload full h2 (overlaps in-flight copies)
    #pragma unroll
    for (int i = 0; i < 32; i++) dynsmem[i * 256 + tid] = g_h2[i * 256 + tid];

    unsigned long long acc[4];
    #pragma unroll
    for (int i = 0; i < 4; i++) acc[i] = 0ull;

    for (int c = 0; c < 64; c++) {
        if (c <= 61)      { asm volatile("cp.async.wait_group 2;"); }
        else if (c == 62) { asm volatile("cp.async.wait_group 1;"); }
        else              { asm volatile("cp.async.wait_group 0;"); }
        __syncthreads();
        if (c + 3 < 64) {
            int cn = c + 3;
            unsigned sb = sbase + 65536 + (cn & 3) * 8192;
            #pragma unroll
            for (int i = 0; i < 2; i++) {
                int lin = i * 256 + tid;
                int row = lin >> 5, u = lin & 31;
                cp16(sb + (row << 9) + (u << 4),
                     gcol + (size_t)(cn * 16 + row) * VOCAB + u * 4);
            }
            asm volatile("cp.async.commit_group;");
        }
        const float* wbuf = (const float*)((char*)dynsmem + 65536 + (c & 3) * 8192);
        #pragma unroll
        for (int kk = 0; kk < 16; kk++) {
            float w = wbuf[kk * 128 + colIdx];
            unsigned long long wq = pack2f(w, w);
            const ulonglong2* hr =
                (const ulonglong2*)(dynsmem + (size_t)(c * 16 + kk) * 8 + half * 4);
            ulonglong2 ha = hr[0], hb = hr[1];
            acc[0] = fma2(ha.x, wq, acc[0]); acc[1] = fma2(ha.y, wq, acc[1]);
            acc[2] = fma2(hb.x, wq, acc[2]); acc[3] = fma2(hb.y, wq, acc[3]);
        }
    }

    float z[8];
    #pragma unroll
    for (int i = 0; i < 4; i++) unpack2(acc[i], z[2 * i], z[2 * i + 1]);

    // stage z: zbuf[b][colIdx] in retired ring space
    float* zbuf = (float*)((char*)dynsmem + 65536);           // 8KB
    __syncthreads();    // all compute done; ring reusable
    #pragma unroll
    for (int j = 0; j < 8; j++)
        zbuf[(half * 8 + j) * 128 + colIdx] = z[j];
    __syncthreads();

    // warp w handles beams 2w, 2w+1: stats + exact top-16 over 128 cols
    #pragma unroll
    for (int bb = 0; bb < 2; bb++) {
        int b = wid * 2 + bb;
        float v0 = zbuf[b * 128 + 0 * 32 + lane];
        float v1 = zbuf[b * 128 + 1 * 32 + lane];
        float v2 = zbuf[b * 128 + 2 * 32 + lane];
        float v3 = zbuf[b * 128 + 3 * 32 + lane];
        // stats on raw z
        float m = fmaxf(fmaxf(v0, v1), fmaxf(v2, v3));
        #pragma unroll
        for (int o = 16; o; o >>= 1) m = fmaxf(m, __shfl_xor_sync(0xffffffffu, m, o));
        float e = expf(v0 - m) + expf(v1 - m) + expf(v2 - m) + expf(v3 - m);
        #pragma unroll
        for (int o = 16; o; o >>= 1) e += __shfl_xor_sync(0xffffffffu, e, o);
        if (lane == 0) g_bstat[blockIdx.x * 16 + b] = make_float2(m, e);
        // keys (with -1000 on last vocab entry)
        unsigned gc0 = blockIdx.x * 128 + 0 * 32 + lane;
        unsigned gc1 = gc0 + 32, gc2 = gc0 + 64, gc3 = gc0 + 96;
        if (gc3 == VOCAB - 1) v3 -= 1000.0f;
        unsigned long long s0 = pack_key(v0, 0xFFFFFFFFu - gc0);
        unsigned long long s1 = pack_key(v1, 0xFFFFFFFFu - gc1);
        unsigned long long s2 = pack_key(v2, 0xFFFFFFFFu - gc2);
        unsigned long long s3 = pack_key(v3, 0xFFFFFFFFu - gc3);
        SORT4(s0, s1, s2, s3)
        #pragma unroll
        for (int r = 0; r < 16; r++) {
            unsigned long long win = warpMaxU64(s0);
            if (s0 == win) { s0 = s1; s1 = s2; s2 = s3; s3 = 0ull; }
            if (lane == r) g_bkeys[((size_t)blockIdx.x * 16 + b) * 16 + r] = win;
        }
    }
}

// combine 250 block partials per beam + fold select(tsel) in last block
__global__ void __launch_bounds__(256) k_reduce(int tsel) {
    int beam = blockIdx.x, tid = threadIdx.x;
    __shared__ float rm[8], rs[8]; __shared__ float s_off;

    float m = -FLT_MAX, s = 0.0f;
    if (tid < NLB) {
        float2 st = g_bstat[tid * 16 + beam];
        m = st.x; s = st.y;
    }
    #pragma unroll
    for (int o = 16; o; o >>= 1) {
        float m2 = __shfl_xor_sync(0xffffffffu, m, o);
        float s2 = __shfl_xor_sync(0xffffffffu, s, o);
        float mm = fmaxf(m, m2);
        s = s * expf(m - mm) + s2 * expf(m2 - mm);
        m = mm;
    }
    if ((tid & 31) == 0) { rm[tid >> 5] = m; rs[tid >> 5] = s; }
    __syncthreads();
    if (tid == 0) {
        float mm = rm[0], ss = rs[0];
        for (int w = 1; w < 8; w++) {
            float m2 = rm[w], s2 = rs[w];
            float mx = fmaxf(mm, m2);
            ss = ss * expf(mm - mx) + s2 * expf(m2 - mx);
            mm = mx;
        }
        s_off = mm + logf(ss);
    }
    __syncthreads();
    float off = s_off;

    unsigned long long sk[16];
    #pragma unroll
    for (int i = 0; i < 16; i++) sk[i] = 0ull;
    if (tid < NLB) {
        const unsigned long long* kp = g_bkeys + ((size_t)tid * 16 + beam) * 16;
        #pragma unroll
        for (int i = 0; i < 16; i++) sk[i] = kp[i];   // sorted desc
    }
    for (int r = 0; r < 16; r++) {
        unsigned long long win = blockMaxU64(sk[0]);
        if (sk[0] == win && win != 0ull) {
            #pragma unroll
            for (int i = 0; i < 15; i++) sk[i] = sk[i + 1];
            sk[15] = 0ull;
        }
        if (tid == 0) {
            g_ti[beam * 16 + r] = (int)(0xFFFFFFFFu - (unsigned)win);
            g_tv[beam * 16 + r] = unpack_val(win) - off;
        }
    }

    // last-block select fold
    __shared__ unsigned s_last;
    __threadfence();
    __syncthreads();
    if (tid == 0) s_last = (atomicAdd(&g_ctr, 1u) == 15u) ? 1u : 0u;
    __syncthreads();
    if (!s_last) return;
    if (tid == 0) g_ctr = 0;
    __threadfence();
    select_body(tsel);
}

__global__ void k_final(float* __restrict__ out) {
    int i = threadIdx.x;
    for (int j = i; j < 528; j += 256) {
        if (j < 256)      out[j] = (float)g_seq[j];
        else if (j < 512) out[j] = g_seqlp[j - 256];
        else              out[j] = g_lps[j - 512];
    }
}

// ---------------- launch ----------------
extern "C" void kernel_launch(void* const* d_in, const int* in_sizes, int n_in,
                              void* d_out, int out_size) {
    const float* state    = (const float*)d_in[0];
    const float* logprobs = (const float*)d_in[1];
    const float* embed    = (const float*)d_in[2];
    const float* W_ih     = (const float*)d_in[3];
    const float* W_hh     = (const float*)d_in[4];
    const float* bvec     = (const float*)d_in[5];
    const float* W_out    = (const float*)d_in[6];
    float* out = (float*)d_out;
    (void)in_sizes; (void)n_in; (void)out_size;

    const int LOGITS_SMEM = 96 * 1024;   // 64KB h2 + 4x8KB ring
    cudaFuncSetAttribute(k_logits, cudaFuncAttributeMaxDynamicSharedMemorySize,
                         LOGITS_SMEM);

    k_begin<<<16, 256>>>(state, logprobs);            // + select(0)
    for (int t = 0; t < TSTEPS - 1; t++) {
        k_rnn<<<dim3(8, 16), 256>>>(embed, W_ih, W_hh);
        k_rnnfin<<<32, 256>>>(bvec);
        k_logits<<<NLB, 256, LOGITS_SMEM>>>(W_out);
        k_reduce<<<16, 256>>>(t + 1);                 // + select(t+1)
    }
    k_final<<<1, 256>>>(out);
}